// round 4
// baseline (speedup 1.0000x reference)
#include <cuda_runtime.h>
#include <cuda_fp16.h>

#define N0V   8192
#define N1V   100000
#define N2V   300000
#define KNBR  32
#define DD    64

#define ROWS_PER_WARP   8
#define WARPS_PER_BLOCK 4

typedef unsigned long long u64t;

// Packed f32x2 helpers (sm_100+ PTX).
#define PACKU64(out, lo, hi) asm("mov.b64 %0, {%1, %2};" : "=l"(out) : "r"(lo), "r"(hi))
#define SPLATU64(out, v)     asm("mov.b64 %0, {%1, %1};" : "=l"(out) : "r"(v))
#define UNPACKU64(lo, hi, in) asm("mov.b64 {%0, %1}, %2;" : "=r"(lo), "=r"(hi) : "l"(in))
#define FFMA2(acc, a, b)     asm("fma.rn.f32x2 %0, %1, %2, %0;" : "+l"(acc) : "l"(a), "l"(b))
#define FADD2(out, a, b)     asm("add.rn.f32x2 %0, %1, %2;" : "=l"(out) : "l"(a), "l"(b))

// Scratch (device globals — allocation in kernel_launch is forbidden).
__device__ __half g_v2h[(size_t)N2V * DD];   // 38.4 MB (L2-resident gather target)
__device__ __half g_h1h[(size_t)N1V * DD];   // 12.8 MB

// ---------------------------------------------------------------------------
// Kernel A: v2h = half(feats[node_ids2]); 2 rows per thread for MLP.
// ---------------------------------------------------------------------------
__global__ void gather_v2h_kernel(const float* __restrict__ feats,
                                  const int*   __restrict__ node_ids2)
{
    int t = blockIdx.x * blockDim.x + threadIdx.x;
    const int half_total = (N2V / 2) * (DD / 4);
    if (t >= half_total) return;
    int row  = t >> 4;
    int c    = t & 15;
    int row2 = row + N2V / 2;
    int s1 = __ldg(node_ids2 + row);
    int s2 = __ldg(node_ids2 + row2);
    float4 v1 = __ldg((const float4*)(feats + (size_t)s1 * DD) + c);
    float4 v2 = __ldg((const float4*)(feats + (size_t)s2 * DD) + c);

    __half2 a0 = __floats2half2_rn(v1.x, v1.y);
    __half2 a1 = __floats2half2_rn(v1.z, v1.w);
    __half2 b0 = __floats2half2_rn(v2.x, v2.y);
    __half2 b1 = __floats2half2_rn(v2.z, v2.w);
    uint2 p1, p2;
    p1.x = *(unsigned int*)&a0;  p1.y = *(unsigned int*)&a1;
    p2.x = *(unsigned int*)&b0;  p2.y = *(unsigned int*)&b1;
    ((uint2*)g_v2h)[(size_t)row  * 16 + c] = p1;
    ((uint2*)g_v2h)[(size_t)row2 * 16 + c] = p2;
}

// ---------------------------------------------------------------------------
// Kernel B/C: one warp per 8 rows.
//  - W held in registers as packed f32x2 pairs (lane owns output cols 2l,2l+1),
//    loaded ONCE per warp (amortized over 8 rows).
//  - Gather-mean: 32 independent 128B row loads/row; neighbor pairs summed
//    with one HADD2 (depth-1 fp16, error negligible) then fp32 accumulated.
//  - Matvec: lane publishes its fp32 (a_2l, a_2l+1) pair to smem (1 STS.64);
//    32 uniform LDS.64 broadcasts + ALU splats feed 64 FFMA2.
// ---------------------------------------------------------------------------
template<bool HALF_OUT>
__global__ void __launch_bounds__(128) agg_mlp_reg2_kernel(
    const __half2* __restrict__ vsrc,   // [nsrc][DD/2]
    const int*     __restrict__ nbr,    // [nrows][KNBR]
    const float*   __restrict__ W,      // [DD][DD] row-major
    const float*   __restrict__ bias,   // [DD]
    void*          __restrict__ outp,   // [nrows][DD] half or float
    int nrows)
{
    __shared__ u64t sPair[WARPS_PER_BLOCK][32];

    const int lane = threadIdx.x & 31;
    const int warp = threadIdx.x >> 5;
    const int row0 = (blockIdx.x * WARPS_PER_BLOCK + warp) * ROWS_PER_WARP;
    if (row0 >= nrows) return;

    // W columns (2l, 2l+1) packed for f32x2 FMA. Loaded once per warp.
    u64t wp[DD];
    #pragma unroll
    for (int d = 0; d < DD; ++d) {
        float2 wv = __ldg((const float2*)W + d * 32 + lane);
        PACKU64(wp[d], __float_as_uint(wv.x), __float_as_uint(wv.y));
    }
    float2 bv = __ldg((const float2*)bias + lane);
    u64t bpack;
    PACKU64(bpack, __float_as_uint(bv.x), __float_as_uint(bv.y));

    #pragma unroll 1
    for (int r = 0; r < ROWS_PER_WARP; ++r) {
        const int row = row0 + r;
        if (row >= nrows) break;

        const int myidx = __ldg(nbr + (size_t)row * KNBR + lane);

        // Gather-mean (fp16 pair-add, fp32 accumulate).
        float sx = 0.f, sy = 0.f;
        #pragma unroll
        for (int k = 0; k < KNBR; k += 2) {
            int i0 = __shfl_sync(0xffffffffu, myidx, k);
            int i1 = __shfl_sync(0xffffffffu, myidx, k + 1);
            __half2 h0 = __ldg(vsrc + (size_t)i0 * (DD / 2) + lane);
            __half2 h1 = __ldg(vsrc + (size_t)i1 * (DD / 2) + lane);
            float2 f = __half22float2(__hadd2(h0, h1));
            sx += f.x;  sy += f.y;
        }
        sx *= (1.0f / KNBR);
        sy *= (1.0f / KNBR);

        // Publish fp32 pair (a_2l, a_2l+1) for broadcast.
        u64t mypair;
        PACKU64(mypair, __float_as_uint(sx), __float_as_uint(sy));
        sPair[warp][lane] = mypair;
        __syncwarp();

        // Matvec: acc(2l,2l+1) += a_d * W[d][2l..2l+1], d = 0..63.
        u64t acc0 = bpack, acc1 = 0ull;
        #pragma unroll
        for (int k = 0; k < 32; ++k) {
            u64t pr = sPair[warp][k];             // uniform LDS.64 broadcast
            unsigned lo, hi;
            UNPACKU64(lo, hi, pr);
            u64t s0, s1;
            SPLATU64(s0, lo);
            SPLATU64(s1, hi);
            FFMA2(acc0, s0, wp[2 * k]);
            FFMA2(acc1, s1, wp[2 * k + 1]);
        }
        __syncwarp();                              // protect sPair for next row

        u64t acct;
        FADD2(acct, acc0, acc1);
        unsigned olo, ohi;
        UNPACKU64(olo, ohi, acct);
        float o0 = fmaxf(__uint_as_float(olo), 0.f);
        float o1 = fmaxf(__uint_as_float(ohi), 0.f);

        if (HALF_OUT) {
            ((__half2*)outp)[(size_t)row * 32 + lane] = __floats2half2_rn(o0, o1);
        } else {
            ((float2*)outp)[(size_t)row * 32 + lane] = make_float2(o0, o1);
        }
    }
}

// ---------------------------------------------------------------------------
// Inputs: 0 feats, 1 W0, 2 b0, 3 W1, 4 b1, 5 neigh_idx0, 6 neigh_idx1,
//         7 node_ids1 (unused), 8 node_ids2
// ---------------------------------------------------------------------------
extern "C" void kernel_launch(void* const* d_in, const int* in_sizes, int n_in,
                              void* d_out, int out_size)
{
    const float* feats      = (const float*)d_in[0];
    const float* W0         = (const float*)d_in[1];
    const float* b0         = (const float*)d_in[2];
    const float* W1         = (const float*)d_in[3];
    const float* b1         = (const float*)d_in[4];
    const int*   neigh_idx0 = (const int*)  d_in[5];
    const int*   neigh_idx1 = (const int*)  d_in[6];
    const int*   node_ids2  = (const int*)  d_in[8];
    float*       out        = (float*)d_out;

    __half* v2h; cudaGetSymbolAddress((void**)&v2h, g_v2h);
    __half* h1h; cudaGetSymbolAddress((void**)&h1h, g_h1h);

    {
        const int half_total = (N2V / 2) * (DD / 4);
        gather_v2h_kernel<<<(half_total + 255) / 256, 256>>>(feats, node_ids2);
    }
    const int rows_per_block = WARPS_PER_BLOCK * ROWS_PER_WARP;  // 32
    agg_mlp_reg2_kernel<true ><<<(N1V + rows_per_block - 1) / rows_per_block, 128>>>(
        (const __half2*)v2h, neigh_idx1, W0, b0, (void*)h1h, N1V);
    agg_mlp_reg2_kernel<false><<<(N0V + rows_per_block - 1) / rows_per_block, 128>>>(
        (const __half2*)h1h, neigh_idx0, W1, b1, (void*)out, N0V);
}

// round 5
// speedup vs baseline: 1.1332x; 1.1332x over previous
#include <cuda_runtime.h>
#include <cuda_fp16.h>

#define N0V   8192
#define N1V   100000
#define N2V   300000
#define KNBR  32
#define DD    64

typedef unsigned long long u64t;

#define PACKU64(out, lo, hi)  asm("mov.b64 %0, {%1, %2};" : "=l"(out) : "f"(lo), "f"(hi))
#define SPLATF64(out, v)      asm("mov.b64 %0, {%1, %1};" : "=l"(out) : "f"(v))
#define UNPACKF64(lo, hi, in) asm("mov.b64 {%0, %1}, %2;" : "=f"(lo), "=f"(hi) : "l"(in))
#define FFMA2(acc, a, b)      asm("fma.rn.f32x2 %0, %1, %2, %0;" : "+l"(acc) : "l"(a), "l"(b))

// Scratch (device globals — allocation in kernel_launch is forbidden).
__device__ __half g_v2h[(size_t)N2V * DD];   // 38.4 MB (L2-resident gather target)
__device__ __half g_h1h[(size_t)N1V * DD];   // 12.8 MB

// ---------------------------------------------------------------------------
// Kernel A: v2h = half(feats[node_ids2]); 2 rows per thread for MLP.
// ---------------------------------------------------------------------------
__global__ void gather_v2h_kernel(const float* __restrict__ feats,
                                  const int*   __restrict__ node_ids2)
{
    int t = blockIdx.x * blockDim.x + threadIdx.x;
    const int half_total = (N2V / 2) * (DD / 4);
    if (t >= half_total) return;
    int row  = t >> 4;
    int c    = t & 15;
    int row2 = row + N2V / 2;
    int s1 = __ldg(node_ids2 + row);
    int s2 = __ldg(node_ids2 + row2);
    float4 v1 = __ldg((const float4*)(feats + (size_t)s1 * DD) + c);
    float4 v2 = __ldg((const float4*)(feats + (size_t)s2 * DD) + c);

    __half2 a0 = __floats2half2_rn(v1.x, v1.y);
    __half2 a1 = __floats2half2_rn(v1.z, v1.w);
    __half2 b0 = __floats2half2_rn(v2.x, v2.y);
    __half2 b1 = __floats2half2_rn(v2.z, v2.w);
    uint2 p1, p2;
    p1.x = *(unsigned int*)&a0;  p1.y = *(unsigned int*)&a1;
    p2.x = *(unsigned int*)&b0;  p2.y = *(unsigned int*)&b1;
    ((uint2*)g_v2h)[(size_t)row  * 16 + c] = p1;
    ((uint2*)g_v2h)[(size_t)row2 * 16 + c] = p2;
}

// ---------------------------------------------------------------------------
// Kernel B/C: block of 256 threads handles 64 output rows.
// Phase 1: 8 warps × 8 rows gather-mean (2 rows interleaved for MLP≈64),
//          fp32 aggregate -> smem tile sAgg[64][66] (padded, conflict-free).
// Phase 2: block GEMM  relu(sAgg @ W + b)  with f32x2 FMAs; thread computes
//          2 rows × 8 cols; W staged in smem, read as 128-bit LDS.
// ---------------------------------------------------------------------------
template<bool HALF_OUT>
__global__ void __launch_bounds__(256) agg_gemm_kernel(
    const __half2* __restrict__ vsrc,   // [nsrc][DD/2]
    const int*     __restrict__ nbr,    // [nrows][KNBR]
    const float*   __restrict__ W,      // [DD][DD] row-major
    const float*   __restrict__ bias,   // [DD]
    void*          __restrict__ outp,   // [nrows][DD] half or float
    int nrows)
{
    __shared__ float sW[DD * DD];       // 16 KB
    __shared__ float sAgg[64][66];      // 16.5 KB, padded

    const int tid  = threadIdx.x;
    const int lane = tid & 31;
    const int warp = tid >> 5;

    // Stage W (coalesced float4).
    #pragma unroll
    for (int i = tid; i < DD * DD / 4; i += 256)
        ((float4*)sW)[i] = __ldg((const float4*)W + i);

    // ---------------- Phase 1: gather-mean into sAgg ----------------
    const int rowbase = blockIdx.x * 64 + warp * 8;
    #pragma unroll 1
    for (int rr = 0; rr < 8; rr += 2) {
        int rA = rowbase + rr;
        int rB = rA + 1;
        int ca = min(rA, nrows - 1);
        int cb = min(rB, nrows - 1);
        int idxA = __ldg(nbr + (size_t)ca * KNBR + lane);
        int idxB = __ldg(nbr + (size_t)cb * KNBR + lane);

        float sxA = 0.f, syA = 0.f, sxB = 0.f, syB = 0.f;
        #pragma unroll
        for (int k = 0; k < KNBR; k += 2) {
            int a0 = __shfl_sync(0xffffffffu, idxA, k);
            int a1 = __shfl_sync(0xffffffffu, idxA, k + 1);
            int b0 = __shfl_sync(0xffffffffu, idxB, k);
            int b1 = __shfl_sync(0xffffffffu, idxB, k + 1);
            __half2 hA0 = __ldg(vsrc + (size_t)a0 * 32 + lane);
            __half2 hA1 = __ldg(vsrc + (size_t)a1 * 32 + lane);
            __half2 hB0 = __ldg(vsrc + (size_t)b0 * 32 + lane);
            __half2 hB1 = __ldg(vsrc + (size_t)b1 * 32 + lane);
            float2 fA = __half22float2(__hadd2(hA0, hA1));
            float2 fB = __half22float2(__hadd2(hB0, hB1));
            sxA += fA.x;  syA += fA.y;
            sxB += fB.x;  syB += fB.y;
        }
        const float inv = 1.0f / KNBR;
        int lr = warp * 8 + rr;
        *(float2*)&sAgg[lr][2 * lane]     = make_float2(sxA * inv, syA * inv);
        *(float2*)&sAgg[lr + 1][2 * lane] = make_float2(sxB * inv, syB * inv);
    }
    __syncthreads();

    // ---------------- Phase 2: GEMM + bias + ReLU ----------------
    const int rp   = tid >> 3;        // 0..31 -> rows 2rp, 2rp+1
    const int col0 = (tid & 7) * 8;   // 8 consecutive output cols

    float4 bv0 = __ldg((const float4*)(bias + col0));
    float4 bv1 = __ldg((const float4*)(bias + col0 + 4));
    u64t acc0[4], acc1[4];
    PACKU64(acc0[0], bv0.x, bv0.y);  PACKU64(acc0[1], bv0.z, bv0.w);
    PACKU64(acc0[2], bv1.x, bv1.y);  PACKU64(acc0[3], bv1.z, bv1.w);
    acc1[0] = acc0[0];  acc1[1] = acc0[1];  acc1[2] = acc0[2];  acc1[3] = acc0[3];

    #pragma unroll
    for (int k = 0; k < DD; ++k) {
        float a0 = sAgg[2 * rp][k];
        float a1 = sAgg[2 * rp + 1][k];
        u64t s0, s1;
        SPLATF64(s0, a0);
        SPLATF64(s1, a1);
        const ulonglong2 w01 = *(const ulonglong2*)&sW[k * DD + col0];
        const ulonglong2 w23 = *(const ulonglong2*)&sW[k * DD + col0 + 4];
        FFMA2(acc0[0], s0, w01.x);  FFMA2(acc0[1], s0, w01.y);
        FFMA2(acc0[2], s0, w23.x);  FFMA2(acc0[3], s0, w23.y);
        FFMA2(acc1[0], s1, w01.x);  FFMA2(acc1[1], s1, w01.y);
        FFMA2(acc1[2], s1, w23.x);  FFMA2(acc1[3], s1, w23.y);
    }

    #pragma unroll
    for (int r = 0; r < 2; ++r) {
        int grow = blockIdx.x * 64 + 2 * rp + r;
        if (grow >= nrows) continue;
        const u64t* acc = r ? acc1 : acc0;
        float o[8];
        #pragma unroll
        for (int j = 0; j < 4; ++j) {
            float lo, hi;
            UNPACKF64(lo, hi, acc[j]);
            o[2 * j]     = fmaxf(lo, 0.f);
            o[2 * j + 1] = fmaxf(hi, 0.f);
        }
        if (HALF_OUT) {
            __half2 h[4];
            #pragma unroll
            for (int j = 0; j < 4; ++j) h[j] = __floats2half2_rn(o[2 * j], o[2 * j + 1]);
            *(uint4*)((__half*)outp + (size_t)grow * DD + col0) = *(uint4*)h;
        } else {
            float* op = (float*)outp + (size_t)grow * DD + col0;
            *(float4*)op       = make_float4(o[0], o[1], o[2], o[3]);
            *(float4*)(op + 4) = make_float4(o[4], o[5], o[6], o[7]);
        }
    }
}

// ---------------------------------------------------------------------------
// Inputs: 0 feats, 1 W0, 2 b0, 3 W1, 4 b1, 5 neigh_idx0, 6 neigh_idx1,
//         7 node_ids1 (unused), 8 node_ids2
// ---------------------------------------------------------------------------
extern "C" void kernel_launch(void* const* d_in, const int* in_sizes, int n_in,
                              void* d_out, int out_size)
{
    const float* feats      = (const float*)d_in[0];
    const float* W0         = (const float*)d_in[1];
    const float* b0         = (const float*)d_in[2];
    const float* W1         = (const float*)d_in[3];
    const float* b1         = (const float*)d_in[4];
    const int*   neigh_idx0 = (const int*)  d_in[5];
    const int*   neigh_idx1 = (const int*)  d_in[6];
    const int*   node_ids2  = (const int*)  d_in[8];
    float*       out        = (float*)d_out;

    __half* v2h; cudaGetSymbolAddress((void**)&v2h, g_v2h);
    __half* h1h; cudaGetSymbolAddress((void**)&h1h, g_h1h);

    {
        const int half_total = (N2V / 2) * (DD / 4);
        gather_v2h_kernel<<<(half_total + 255) / 256, 256>>>(feats, node_ids2);
    }
    agg_gemm_kernel<true ><<<(N1V + 63) / 64, 256>>>(
        (const __half2*)v2h, neigh_idx1, W0, b0, (void*)h1h, N1V);
    agg_gemm_kernel<false><<<(N0V + 63) / 64, 256>>>(
        (const __half2*)h1h, neigh_idx0, W1, b1, (void*)out, N0V);
}